// round 8
// baseline (speedup 1.0000x reference)
#include <cuda_runtime.h>
#include <cfloat>

// xp: (32, 64, 64, 512) fp32, m innermost. out: (32, 48*512), bin = iw*6+ih.
// Resize is identity. Row bins: 8 rows each. Col edges: {0,11,21,32,43,53,64}.
//
// R8 (final drain experiment): the session's evidence (R1-R7) shows the
// kernel is pinned at the chip's path-independent LTS cap (~6.3-6.4 TB/s);
// only ramp/drain headroom (~1.5%) remains. This variant minimizes thread
// lifetime while keeping R3's best-measured inner loop: 512 threads = 4
// row-quads x 128 channel lanes; each thread runs exactly ONE row-pair body
// (2 rows x 10/11 cols = 20-22 independent LDG.128, fully unrolled), then a
// 6KB smem tree merge. Lifetime = 1/4 of R3 -> shortest possible in-flight
// decay at grid end; zero extra traffic, zero extra launches.

#define B_DIM 32
#define W_DIM 64
#define H_DIM 64
#define M_DIM 512
#define W_BINS 8
#define H_BINS 6
#define M4 (M_DIM / 4)            // 128 float4 lanes per (b,r,c)
#define ROW_STRIDE (H_DIM * M4)   // float4 elems per image row

__constant__ int C_EDGE[H_BINS + 1] = {0, 11, 21, 32, 43, 53, 64};

static __device__ __forceinline__ float4 fmax4(float4 a, float4 b) {
    a.x = fmaxf(a.x, b.x);
    a.y = fmaxf(a.y, b.y);
    a.z = fmaxf(a.z, b.z);
    a.w = fmaxf(a.w, b.w);
    return a;
}

// Block = (bin, b). 512 threads: quad q = t>>7 covers rows [r1+2q, r1+2q+2),
// lane = t&127 owns channels [4*lane, 4*lane+4).
__global__ __launch_bounds__(4 * M4, 1)
void adaptive_maxpool_kernel(const float4* __restrict__ x4,
                             float4* __restrict__ out4) {
    const int bin = blockIdx.x;       // 0..47  (iw*6 + ih)
    const int b   = blockIdx.y;       // 0..31
    const int iw  = bin / H_BINS;
    const int ih  = bin - iw * H_BINS;

    const int t    = threadIdx.x;     // 0..511
    const int lane = t & (M4 - 1);    // 0..127
    const int q    = t >> 7;          // 0..3

    const int r1 = iw * (W_DIM / W_BINS) + q * 2;   // this quad's 2 rows
    const int c1 = C_EDGE[ih];
    const bool has11 = (C_EDGE[ih + 1] - c1) == 11; // widths are 10 or 11

    const float4* r0 =
        x4 + ((size_t)(b * W_DIM + r1) * H_DIM + c1) * M4 + lane;
    const float4* r1p = r0 + ROW_STRIDE;

    float4 acc = make_float4(-FLT_MAX, -FLT_MAX, -FLT_MAX, -FLT_MAX);

    // One row-pair body: 2x10 (+2) independent 16B loads, fully unrolled.
    #pragma unroll
    for (int c = 0; c < 10; ++c) {
        float4 va = __ldcs(r0  + (size_t)c * M4);
        float4 vb = __ldcs(r1p + (size_t)c * M4);
        acc = fmax4(acc, fmax4(va, vb));
    }
    if (has11) {
        float4 va = __ldcs(r0  + (size_t)10 * M4);
        float4 vb = __ldcs(r1p + (size_t)10 * M4);
        acc = fmax4(acc, fmax4(va, vb));
    }

    // Merge the 4 quads through smem (6KB); quad 0 reduces and stores.
    __shared__ float4 sh[3][M4];
    if (q > 0) sh[q - 1][lane] = acc;
    __syncthreads();
    if (q == 0) {
        acc = fmax4(acc, sh[0][lane]);
        acc = fmax4(acc, fmax4(sh[1][lane], sh[2][lane]));
        out4[((size_t)b * (W_BINS * H_BINS) + bin) * M4 + lane] = acc;
    }
}

extern "C" void kernel_launch(void* const* d_in, const int* in_sizes, int n_in,
                              void* d_out, int out_size) {
    (void)in_sizes; (void)n_in; (void)out_size;
    const float4* x4 = (const float4*)d_in[0];
    float4* o4 = (float4*)d_out;

    dim3 grid(W_BINS * H_BINS, B_DIM);   // (48, 32) = 1536 blocks
    adaptive_maxpool_kernel<<<grid, 4 * M4>>>(x4, o4);
}